// round 4
// baseline (speedup 1.0000x reference)
#include <cuda_runtime.h>
#include <cstdint>

#define BATCH 16
#define NA    8400
#define NC    80
#define NM    24
#define KTOP  13
#define REG   16
#define CH    256
#define CHUNKS 33   // ceil(8400/256)

// ---------------- device scratch ----------------
__device__ unsigned long long g_best[BATCH * NA];
__device__ unsigned long long g_cand[BATCH * NM * CHUNKS * KTOP];
__device__ float g_mx[BATCH * NA];
__device__ float g_partial[BATCH][CHUNKS][8];
__device__ int   g_ctr_main[BATCH];   // zero-initialized; self-resetting
__device__ int   g_ctr_loss;          // zero-initialized; self-resetting

// ---------------- helpers ----------------
__device__ __forceinline__ float sigmoidf(float x) { return 1.0f / (1.0f + expf(-x)); }

__device__ __forceinline__ float iou_box(float a0, float a1, float a2, float a3,
                                         float b0, float b1, float b2, float b3) {
    float lt0 = fmaxf(a0, b0), lt1 = fmaxf(a1, b1);
    float rb0 = fminf(a2, b2), rb1 = fminf(a3, b3);
    float w = fmaxf(rb0 - lt0, 0.0f), h = fmaxf(rb1 - lt1, 0.0f);
    float inter = w * h;
    float aa = fmaxf(a2 - a0, 0.0f) * fmaxf(a3 - a1, 0.0f);
    float ab = fmaxf(b2 - b0, 0.0f) * fmaxf(b3 - b1, 0.0f);
    return inter / (aa + ab - inter + 1e-7f);
}

// dtype auto-detect (validated): cmask float32/int32/uint8, labels int32/float32
__device__ __forceinline__ void detect_modes(const void* cm, const void* lab, int b,
                                             int* cmode_out, int* lmode_out) {
    const unsigned* cw = (const unsigned*)cm;
    int cmode;
    if (cw[0] == 0x3F800000u) cmode = 0;
    else {
        cmode = 1;
        for (int i = 0; i < 80; i++) if (cw[i] > 1u) { cmode = 2; break; }
    }
    const unsigned* lw = (const unsigned*)lab;
    int lm = 0;
    for (int i = 0; i < NM; i++) if (lw[b * NM + i] > 1000u) { lm = 1; break; }
    *cmode_out = cmode; *lmode_out = lm;
}

__device__ __forceinline__ float load_cmask(const void* cm, int cmode, int b, int c) {
    float v;
    if (cmode == 0)      v = ((const float*)cm)[b * NC + c];
    else if (cmode == 1) v = (float)(((const int*)cm)[b * NC + c] != 0);
    else                 v = (float)(((const unsigned char*)cm)[b * NC + c] != 0);
    return (v != 0.0f) ? 1.0f : 0.0f;
}

__device__ __forceinline__ int load_label(const void* lab, int lmode, int b, int g) {
    return lmode ? (int)(((const float*)lab)[b * NM + g]) : ((const int*)lab)[b * NM + g];
}

// ============ k_main: masked max + align + local top-13 + (last block) merge/scatter ============
__global__ __launch_bounds__(256) void k_main(const float* __restrict__ pb,
                                              const float* __restrict__ ps,
                                              const float* __restrict__ ap,
                                              const float* __restrict__ gtb,
                                              const void* __restrict__ cm_raw,
                                              const void* __restrict__ lab_raw) {
    __shared__ float cm_s[NC];
    __shared__ float4 cm4_s[20];
    __shared__ int   lab_s[NM];
    __shared__ int   val_s[NM];
    __shared__ float4 gtb_s[NM];
    __shared__ int   det_s[2];
    __shared__ float pm[8][32][21];           // per-warp per-anchor lane-partial maxima
    __shared__ float align_s[NM][CH + 1];
    __shared__ int   is_last;

    int chunk = blockIdx.x, b = blockIdx.y, t = threadIdx.x;
    int lane = t & 31, w = t >> 5;
    int nbase = chunk * CH;

    if (t == 0) detect_modes(cm_raw, lab_raw, b, &det_s[0], &det_s[1]);
    __syncthreads();
    int cmode = det_s[0], lmode = det_s[1];

    if (t < NC) cm_s[t] = load_cmask(cm_raw, cmode, b, t);
    if (t < NM) {
        int lb = load_label(lab_raw, lmode, b, t);
        lab_s[t] = min(max(lb, 0), NC - 1);
        val_s[t] = (lb >= 0 && lb < NC) ? 1 : 0;
        gtb_s[t] = ((const float4*)gtb)[b * NM + t];
    }
    __syncthreads();
    if (t < NM) val_s[t] = val_s[t] && (cm_s[lab_s[t]] != 0.0f);
    if (t < 20) cm4_s[t] = ((const float4*)cm_s)[t];
#pragma unroll 4
    for (int g = 0; g < NM; g++) align_s[g][t] = -1.0f;
    if (nbase + t < NA) g_best[b * NA + nbase + t] = 0ull;
    __syncthreads();

    int a0 = nbase + w * 32;
    int alim = min(32, NA - a0);          // warp-uniform (can be <=0 in last chunk)

    // Phase A: coalesced score read, lane-partial masked max -> smem (no cross-lane deps)
    if (alim > 0 && lane < 20) {
        const float4* row4 = (const float4*)(ps + ((size_t)b * NA + a0) * NC);
        float4 m4 = cm4_s[lane];
        for (int a = 0; a < alim; a++) {
            float4 s4 = row4[(size_t)a * 20 + lane];
            float m = -1e30f;
            m = fmaxf(m, m4.x != 0.0f ? s4.x : -1e30f);
            m = fmaxf(m, m4.y != 0.0f ? s4.y : -1e30f);
            m = fmaxf(m, m4.z != 0.0f ? s4.z : -1e30f);
            m = fmaxf(m, m4.w != 0.0f ? s4.w : -1e30f);
            pm[w][a][lane] = m;
        }
    }
    __syncwarp();

    // Phase B: each lane reduces its own anchor's 20 partials (conflict-free, coalesced store)
    if (lane < alim) {
        float m = -1e30f;
#pragma unroll
        for (int j = 0; j < 20; j++) m = fmaxf(m, pm[w][lane][j]);
        g_mx[b * NA + a0 + lane] = m;
    }

    // Phase C: align, lane owns anchor, loop GTs (smem broadcast)
    int n = a0 + lane;
    if (n < NA && alim > 0) {
        float2 apc = ((const float2*)ap)[n];
        float4 pbx = ((const float4*)pb)[(size_t)b * NA + n];
        const float* srow = ps + ((size_t)b * NA + n) * NC;   // L1-hot (phase A)
#pragma unroll 4
        for (int g = 0; g < NM; g++) {
            float4 gbx = gtb_s[g];
            bool inside = val_s[g] && apc.x >= gbx.x && apc.x <= gbx.z &&
                          apc.y >= gbx.y && apc.y <= gbx.w;
            if (inside) {
                float iou = iou_box(pbx.x, pbx.y, pbx.z, pbx.w, gbx.x, gbx.y, gbx.z, gbx.w);
                float cls = sigmoidf(srow[lab_s[g]]);
                float i2 = iou * iou;
                align_s[g][w * 32 + lane] = cls * (i2 * i2 * i2);
            }
        }
    }
    __syncthreads();

    // Phase D: local top-13; warp w handles GTs w, w+8, w+16
#pragma unroll
    for (int gi = 0; gi < 3; gi++) {
        int g = w + gi * 8;
        unsigned long long key[8];
        unsigned ball[8];
        int base[8], tot = 0;
#pragma unroll
        for (int r = 0; r < 8; r++) {
            float v = align_s[g][lane + 32 * r];
            int nn = nbase + lane + 32 * r;
            key[r] = (v >= 0.0f)
                ? (((unsigned long long)__float_as_uint(v) << 32) | (unsigned)(0xFFFFFFFFu - nn))
                : 0ull;
            ball[r] = __ballot_sync(~0u, key[r] != 0ull);
            base[r] = tot;
            tot += __popc(ball[r]);
        }
        unsigned long long* outc = g_cand + (((size_t)b * NM + g) * CHUNKS + chunk) * KTOP;

        if (tot <= KTOP) {
            unsigned lt = (1u << lane) - 1u;
#pragma unroll
            for (int r = 0; r < 8; r++) {
                if (key[r] != 0ull) {
                    int slot = base[r] + __popc(ball[r] & lt);
                    outc[slot] = key[r];
                }
            }
            if (lane >= tot && lane < KTOP) outc[lane] = 0ull;
        } else {
            for (int k = 0; k < KTOP; k++) {
                unsigned long long lm = key[0]; int lr = 0;
#pragma unroll
                for (int r = 1; r < 8; r++) if (key[r] > lm) { lm = key[r]; lr = r; }
                unsigned long long wm = lm;
#pragma unroll
                for (int o = 16; o > 0; o >>= 1) {
                    unsigned long long oth = __shfl_xor_sync(~0u, wm, o);
                    if (oth > wm) wm = oth;
                }
                if (lm == wm) key[lr] = 0ull;
                if (lane == 0) outc[k] = wm;
            }
        }
    }

    // ---- last block of this batch performs merge + scatter (fused old k_merge) ----
    __threadfence();
    __syncthreads();
    if (t == 0) is_last = (atomicAdd(&g_ctr_main[b], 1) == CHUNKS - 1);
    __syncthreads();
    if (!is_last) return;
    if (t == 0) g_ctr_main[b] = 0;   // reset for next graph replay
    __threadfence();                 // acquire all blocks' g_cand writes

#pragma unroll
    for (int gi = 0; gi < 3; gi++) {
        int g = w + gi * 8;
        const unsigned long long* src = g_cand + ((size_t)b * NM + g) * CHUNKS * KTOP;
        unsigned long long key[14];
#pragma unroll
        for (int r = 0; r < 14; r++) {
            int e = lane + 32 * r;
            key[r] = (e < CHUNKS * KTOP) ? src[e] : 0ull;
        }
        unsigned pri = (unsigned)(NM - g);
        for (int k = 0; k < KTOP; k++) {
            unsigned long long lm = key[0]; int lr = 0;
#pragma unroll
            for (int r = 1; r < 14; r++) if (key[r] > lm) { lm = key[r]; lr = r; }
            unsigned long long wm = lm;
#pragma unroll
            for (int o = 16; o > 0; o >>= 1) {
                unsigned long long oth = __shfl_xor_sync(~0u, wm, o);
                if (oth > wm) wm = oth;
            }
            if (wm == 0ull) break;
            if (lm == wm) {
                key[lr] = 0ull;
                int nn = (int)(0xFFFFFFFFu - (unsigned)(wm & 0xFFFFFFFFull));
                unsigned long long key2 = (wm & 0xFFFFFFFF00000000ull) | pri;
                atomicMax(&g_best[b * NA + nn], key2);
            }
        }
    }
}

// ============ k_loss (+ fused final in global last block) ============
__global__ __launch_bounds__(256) void k_loss(const float* __restrict__ pb,
                                              const float* __restrict__ ps,
                                              const float* __restrict__ pobj,
                                              const float* __restrict__ ap,
                                              const float* __restrict__ st,
                                              const float* __restrict__ bd,
                                              const float* __restrict__ gtb,
                                              const void* __restrict__ cm_raw,
                                              const void* __restrict__ lab_raw,
                                              float* __restrict__ out) {
    __shared__ float cm_s[NC];
    __shared__ int   lab_s[NM];
    __shared__ int   det_s[2];
    __shared__ float wred[8 * 8];
    __shared__ int   is_last;
    __shared__ float img[BATCH][8];

    int b = blockIdx.y, t = threadIdx.x;
    int lane = t & 31, w = t >> 5;
    int n = blockIdx.x * CH + t;

    if (t == 0) detect_modes(cm_raw, lab_raw, b, &det_s[0], &det_s[1]);
    __syncthreads();
    if (t < NC) cm_s[t] = load_cmask(cm_raw, det_s[0], b, t);
    if (t < NM) {
        int lb = load_label(lab_raw, det_s[1], b, t);
        lab_s[t] = min(max(lb, 0), NC - 1);
    }
    __syncthreads();

    // acc: 0 focal, 1 cnt, 2 (1-ciou), 3 matched iou, 4 ce, 5 dfl, 6 pos, 7 neg
    float acc[8];
#pragma unroll
    for (int q = 0; q < 8; q++) acc[q] = 0.0f;

    if (n < NA) {
        unsigned long long key = g_best[b * NA + n];
        bool fg = (key != 0ull);

        float x = pobj[(size_t)b * NA + n];
        float tt = fg ? 1.0f : 0.0f;
        float ce_o = fmaxf(x, 0.0f) - x * tt + log1pf(expf(-fabsf(x)));
        float prob_o = sigmoidf(x);
        float p_t = fg ? prob_o : (1.0f - prob_o);
        float af  = fg ? 0.25f  : 0.75f;
        float om  = 1.0f - p_t;
        acc[0] = ce_o * af * om * om;

        float mx = g_mx[b * NA + n];

        if (!fg) {
            acc[7] = prob_o * sigmoidf(mx);
        } else {
            int g = NM - (int)(key & 0xFFFFFFFFull);
            int lab = lab_s[g];
            const float* srow = ps + ((size_t)b * NA + n) * NC;
            float slab = srow[lab];
            float sum = 0.0f;
            for (int c = 0; c < NC; c++)
                if (cm_s[c] != 0.0f) sum += expf(srow[c] - mx);
            float lse = mx + logf(sum);
            acc[4] = lse - slab;
            acc[6] = prob_o * sigmoidf(slab);
            acc[1] = 1.0f;

            float4 a4 = ((const float4*)pb)[(size_t)b * NA + n];
            float4 b4 = ((const float4*)gtb)[b * NM + g];
            float a0 = a4.x, a1 = a4.y, a2 = a4.z, a3 = a4.w;
            float b0 = b4.x, b1 = b4.y, b2 = b4.z, b3 = b4.w;

            float iou = iou_box(a0, a1, a2, a3, b0, b1, b2, b3);
            acc[3] = iou;

            float cw = fmaxf(a2, b2) - fminf(a0, b0);
            float ch = fmaxf(a3, b3) - fminf(a1, b1);
            float c2 = cw * cw + ch * ch + 1e-7f;
            float dx = a0 + a2 - b0 - b2;
            float dy = a1 + a3 - b1 - b3;
            float rho2 = (dx * dx + dy * dy) * 0.25f;
            float w1 = a2 - a0, h1 = a3 - a1;
            float w2 = b2 - b0, h2 = b3 - b1;
            float dat = atanf(w2 / (h2 + 1e-7f)) - atanf(w1 / (h1 + 1e-7f));
            float v = (4.0f / (3.14159265358979323846f * 3.14159265358979323846f)) * dat * dat;
            float alpha = v / (v - iou + 1.0f + 1e-7f);
            float ciou = iou - rho2 / c2 - v * alpha;
            acc[2] = 1.0f - ciou;

            float2 apc = ((const float2*)ap)[n];
            float s = st[n];
            float tgt[4];
            tgt[0] = (apc.x - b0) / s;
            tgt[1] = (apc.y - b1) / s;
            tgt[2] = (b2 - apc.x) / s;
            tgt[3] = (b3 - apc.y) / s;
            const float* lrow = bd + ((size_t)b * NA + n) * (4 * REG);
            float dfl = 0.0f;
#pragma unroll
            for (int j = 0; j < 4; j++) {
                float tv = fminf(fmaxf(tgt[j], 0.0f), (float)(REG - 1) - 0.01f);
                int tl = (int)tv;
                int tr = min(tl + 1, REG - 1);
                float wl = (float)tr - tv;
                float wr = 1.0f - wl;
                const float* lg = lrow + j * REG;
                float m2 = -1e30f;
#pragma unroll
                for (int i = 0; i < REG; i++) m2 = fmaxf(m2, lg[i]);
                float s2 = 0.0f;
#pragma unroll
                for (int i = 0; i < REG; i++) s2 += expf(lg[i] - m2);
                float lse2 = m2 + logf(s2);
                dfl += (lse2 - lg[tl]) * wl + (lse2 - lg[tr]) * wr;
            }
            acc[5] = dfl;
        }
    }

#pragma unroll
    for (int q = 0; q < 8; q++) {
        float v = acc[q];
#pragma unroll
        for (int o = 16; o > 0; o >>= 1) v += __shfl_xor_sync(~0u, v, o);
        if (lane == 0) wred[w * 8 + q] = v;
    }
    __syncthreads();
    if (t < 8) {
        float s = 0.0f;
#pragma unroll
        for (int ww = 0; ww < 8; ww++) s += wred[ww * 8 + t];
        g_partial[b][blockIdx.x][t] = s;
    }

    // ---- global last block computes the final scalars (fused old k_final) ----
    __threadfence();
    __syncthreads();
    if (t == 0) is_last = (atomicAdd(&g_ctr_loss, 1) == CHUNKS * BATCH - 1);
    __syncthreads();
    if (!is_last) return;
    if (t == 0) g_ctr_loss = 0;      // reset for next graph replay
    __threadfence();                 // acquire all blocks' g_partial writes

    if (t < BATCH * 8) {
        int b2 = t >> 3, q = t & 7;
        float s = 0.0f;
#pragma unroll
        for (int c = 0; c < CHUNKS; c++) s += g_partial[b2][c][q];
        img[b2][q] = s;
    }
    __syncthreads();
    if (t == 0) {
        float tot_obj = 0, tot_iou = 0, tot_match = 0, tot_dfl = 0;
        float tot_pos = 0, miou = 0, pos = 0, neg = 0;
        for (int b2 = 0; b2 < BATCH; b2++) {
            float cnt = img[b2][1];
            float cs = fmaxf(cnt, 1.0f);
            tot_obj   += img[b2][0] / (float)NA;
            tot_iou   += img[b2][2] / cs;
            tot_match += img[b2][4] / cs;
            tot_dfl   += img[b2][5] / (4.0f * cs);
            tot_pos   += cnt;
            miou += img[b2][3];
            pos  += img[b2][6];
            neg  += img[b2][7];
        }
        float tot_neg = (float)(BATCH * NA) - tot_pos;
        float nb = (float)BATCH;
        float loss = (tot_obj + tot_match + 7.5f * tot_iou + 1.5f * tot_dfl) / nb;
        out[0] = loss;
        out[1] = tot_obj / nb;
        out[2] = tot_match / nb;
        out[3] = tot_iou / nb;
        out[4] = tot_dfl / nb;
        out[5] = tot_pos;
        out[6] = tot_neg;
        out[7] = pos / fmaxf(tot_pos, 1.0f);
        out[8] = neg / fmaxf(tot_neg, 1.0f);
        out[9] = miou / fmaxf(tot_pos, 1.0f);
    }
}

// ---------------- launch ----------------
extern "C" void kernel_launch(void* const* d_in, const int* in_sizes, int n_in,
                              void* d_out, int out_size) {
    const float* pred_boxes    = (const float*)d_in[0];
    const float* pred_scores   = (const float*)d_in[1];
    const float* pred_obj      = (const float*)d_in[2];
    const float* anchor_points = (const float*)d_in[3];
    const float* stride_tensor = (const float*)d_in[4];
    const float* box_dist      = (const float*)d_in[5];
    const void*  class_mask    = d_in[6];
    const float* gt_boxes      = (const float*)d_in[7];
    const void*  gt_labels     = d_in[8];
    float* out = (float*)d_out;

    dim3 g(CHUNKS, BATCH);
    k_main<<<g, 256>>>(pred_boxes, pred_scores, anchor_points, gt_boxes,
                       class_mask, gt_labels);
    k_loss<<<g, 256>>>(pred_boxes, pred_scores, pred_obj, anchor_points,
                       stride_tensor, box_dist, gt_boxes, class_mask, gt_labels, out);
}